// round 17
// baseline (speedup 1.0000x reference)
#include <cuda_runtime.h>
#include <cuda_fp16.h>
#include <math.h>
#include <stdint.h>

#define BB 1024
#define TT 200
#define EE 64

// ---------------- scratch (__device__ globals: allocation-free) ----------------
__device__ float g_X [BB * 448];
__device__ float g_Z1[BB * 512];
__device__ float g_Z2[BB * 256];
// column-stat accumulators: [0,448)=X, [448,960)=Z1, [960,1216)=Z2
__device__ float g_cs[1216], g_cq[1216];
// fp16 operand images, plain [n][k] row-major packed as half2 along k
__device__ unsigned g_imgBbc[16384];   // (W1b - W1c)^T  [256][64 half2]
__device__ unsigned g_imgBd [16384];   // (W1d)^T        [256][64 half2]
__device__ unsigned g_imgW2T[16384];   // W2^T           [128][128 half2]
__device__ unsigned g_W1ach[128 * 128]; // W1a + W1c, [k][j] as half2 pairs along j

__device__ __forceinline__ float sigm(float x) { return 1.0f / (1.0f + __expf(-x)); }

__device__ __forceinline__ unsigned pack2(float a, float b) {
    __half2 h = __floats2half2_rn(a, b);
    return *reinterpret_cast<unsigned*>(&h);
}
__device__ __forceinline__ unsigned hfma2u(unsigned c2, unsigned d2, unsigned b2v) {
    __half2 r = __hfma2(*reinterpret_cast<__half2*>(&c2),
                        *reinterpret_cast<__half2*>(&d2),
                        *reinterpret_cast<__half2*>(&b2v));
    return *reinterpret_cast<unsigned*>(&r);
}

// warp-level HMMA: D(16x8,f32) += A(16x16,f16 row) * B(16x8,f16 col)
__device__ __forceinline__ void mma16816(float* d, const unsigned* a,
                                         unsigned b0, unsigned b1) {
    asm volatile(
        "mma.sync.aligned.m16n8k16.row.col.f32.f16.f16.f32 "
        "{%0,%1,%2,%3}, {%4,%5,%6,%7}, {%8,%9}, {%0,%1,%2,%3};"
        : "+f"(d[0]), "+f"(d[1]), "+f"(d[2]), "+f"(d[3])
        : "r"(a[0]), "r"(a[1]), "r"(a[2]), "r"(a[3]), "r"(b0), "r"(b1));
}

// ldmatrix x4: four 8x8 b16 matrices; lane i supplies row address of matrix i/8
__device__ __forceinline__ void ldsm4(unsigned r[4], uint32_t saddr) {
    asm volatile("ldmatrix.sync.aligned.m8n8.x4.shared.b16 {%0,%1,%2,%3}, [%4];"
        : "=r"(r[0]), "=r"(r[1]), "=r"(r[2]), "=r"(r[3]) : "r"(saddr));
}

// =====================================================================
// prep_all: all b-invariant fp16 operand images + zero stat accumulators
// =====================================================================
__global__ void __launch_bounds__(256) prep_all(const float* __restrict__ w1,
                                                const float* __restrict__ w2)
{
    int gid = blockIdx.x * 256 + threadIdx.x;
    if (gid < 16384) {
        int j = gid >> 6, kk = gid & 63, k = kk * 2;
        float bc0 = w1[(128 + k) * 256 + j] - w1[(256 + k) * 256 + j];
        float bc1 = w1[(129 + k) * 256 + j] - w1[(257 + k) * 256 + j];
        g_imgBbc[gid] = pack2(bc0, bc1);
        g_imgBd [gid] = pack2(w1[(384 + k) * 256 + j], w1[(385 + k) * 256 + j]);
    } else if (gid < 32768) {
        int t = gid - 16384;
        int j = t >> 7, kk = t & 127, k = kk * 2;
        g_imgW2T[t] = pack2(w2[k * 128 + j], w2[(k + 1) * 128 + j]);
    } else {
        int t = gid - 32768;                  // 16384 half2 elems, [k][j2]
        int k = t >> 7, j = (t & 127) * 2;
        float a = w1[k * 256 + j]     + w1[(256 + k) * 256 + j];
        float b = w1[k * 256 + j + 1] + w1[(256 + k) * 256 + j + 1];
        g_W1ach[t] = pack2(a, b);
        if (t < 1216) { g_cs[t] = 0.f; g_cq[t] = 0.f; }
    }
}

// =====================================================================
// FUSED per-b kernel (512 threads, 16 warps); smem layout as R13
// =====================================================================
#define LDA1 136
#define LDB1 136
#define LD2  264
#define OFF_A2 0
#define OFF_B  105600
#define OFF_A1 175232
#define OFF_C1 229632
#define OFF_CH 230656
#define FUSED_SMEM 231936
#define FTH 512

__global__ void __launch_bounds__(FTH) fused_kernel(
    const int* __restrict__ uid, const int* __restrict__ mid,
    const int* __restrict__ catid,
    const int* __restrict__ hmid, const int* __restrict__ hcat,
    const int* __restrict__ mask,
    const float* __restrict__ user_table, const float* __restrict__ mat_table,
    const float* __restrict__ cat_table,
    const float* __restrict__ b1, const float* __restrict__ b2,
    const float* __restrict__ w3, const float* __restrict__ b3)
{
    extern __shared__ __align__(16) char sm[];
    __half* A2 = reinterpret_cast<__half*>(sm + OFF_A2);
    __half* Bw = reinterpret_cast<__half*>(sm + OFF_B);
    __half* A1 = reinterpret_cast<__half*>(sm + OFF_A1);
    float*  c1s = reinterpret_cast<float*>(sm + OFF_C1);
    unsigned* curs2h = reinterpret_cast<unsigned*>(sm + OFF_CH);
    // misc overlay (valid only after GEMM1 + sync)
    float* s_aw  = reinterpret_cast<float*>(sm + OFF_A1);
    float* s_w3  = reinterpret_cast<float*>(sm + OFF_A1 + 832);
    float* s_b2  = reinterpret_cast<float*>(sm + OFF_A1 + 1344);
    float* s_lau = reinterpret_cast<float*>(sm + OFF_A1 + 1856);
    float* s_hs  = reinterpret_cast<float*>(sm + OFF_A1 + 2368);
    float* s_red = reinterpret_cast<float*>(sm + OFF_A1 + 2880);
    float* s_scal= reinterpret_cast<float*>(sm + OFF_A1 + 3008); // max,sum,cnt

    const int b = blockIdx.x, tid = threadIdx.x;
    const int wid = tid >> 5, lane = tid & 31;
    const int g = lane >> 2, t4 = lane & 3;
    const uint32_t smsh = (uint32_t)__cvta_generic_to_shared(sm);

    // LDSM lane selectors
    const int rowsel = lane & 15;
    const int kselA = (lane & 16) ? 8 : 0;
    const int nsel = (lane & 7) + ((lane >> 4) & 1) * 8;
    const int kselB = (lane & 8) ? 8 : 0;

    // ---- prologue: cur as half2 ----
    if (tid < 64) {
        int c0 = 2 * tid;
        float v0 = (c0 < 64) ? mat_table[(size_t)mid[b] * EE + c0]
                             : cat_table[(size_t)catid[b] * EE + c0 - 64];
        float v1 = (c0 + 1 < 64) ? mat_table[(size_t)mid[b] * EE + c0 + 1]
                                 : cat_table[(size_t)catid[b] * EE + c0 + 1 - 64];
        curs2h[tid] = pack2(v0, v1);
    }
    __syncthreads();

    // ---- c1 (warps 0-3) ----
    if (tid < 128) {
        const int j2 = tid;
        float acc0 = b1[2 * j2], acc1 = b1[2 * j2 + 1];
#pragma unroll 8
        for (int kk = 0; kk < 64; kk++) {
            unsigned cu = curs2h[kk];
            __half2 c2 = *reinterpret_cast<__half2*>(&cu);
            float clo = __low2float(c2), chi = __high2float(c2);
            unsigned w0 = g_W1ach[(2 * kk) * 128 + j2];
            unsigned w1v = g_W1ach[(2 * kk + 1) * 128 + j2];
            __half2 h0 = *reinterpret_cast<__half2*>(&w0);
            __half2 h1 = *reinterpret_cast<__half2*>(&w1v);
            acc0 += clo * __low2float(h0)  + chi * __low2float(h1);
            acc1 += clo * __high2float(h0) + chi * __high2float(h1);
        }
        c1s[2 * j2] = acc0;
        c1s[2 * j2 + 1] = acc1;
    }
    // ---- Weff^T [256][128] fp16 into B region ----
    {
        unsigned ch = curs2h[tid & 63];
        for (int t = tid; t < 16384; t += FTH) {
            int j = t >> 6, kk = t & 63;
            *reinterpret_cast<unsigned*>(&Bw[j * LDB1 + kk * 2]) =
                hfma2u(ch, g_imgBd[t], g_imgBbc[t]);
        }
    }
    // ---- A1 = hist fp16, 200 rows ----
    for (int t = tid; t < 3200; t += FTH) {
        int r = t >> 4, kg = t & 15;
        const float* src = (kg < 8)
            ? (mat_table + (size_t)hmid[b * TT + r] * EE + kg * 8)
            : (cat_table + (size_t)hcat[b * TT + r] * EE + (kg - 8) * 8);
        float4 f0 = *reinterpret_cast<const float4*>(src);
        float4 f1 = *reinterpret_cast<const float4*>(src + 4);
        uint4 o;
        o.x = pack2(f0.x, f0.y); o.y = pack2(f0.z, f0.w);
        o.z = pack2(f1.x, f1.y); o.w = pack2(f1.z, f1.w);
        *reinterpret_cast<uint4*>(&A1[r * LDA1 + kg * 8]) = o;
    }
    __syncthreads();

    // ---- GEMM1: warp owns n-strip (32 cols), chunks of <=4 m-tiles, LDSM ----
    {
        const int s = wid >> 1;                 // n-strip 0..7
        const int h = wid & 1;
        const int mstart = h ? 7 : 0;
        const int mcount = h ? 6 : 7;
        const uint32_t aBase = smsh + OFF_A1 + (uint32_t)(rowsel * LDA1 + kselA) * 2;
        const uint32_t bBase = smsh + OFF_B +
            (uint32_t)((s * 32 + nsel) * LDB1 + kselB) * 2;
        for (int cbase = 0; cbase < mcount; cbase += 4) {
            const int M = (mcount - cbase < 4) ? (mcount - cbase) : 4;
            float d[4][4][4];
#pragma unroll
            for (int mi = 0; mi < 4; mi++)
                for (int n8 = 0; n8 < 4; n8++)
                    { d[mi][n8][0]=0.f; d[mi][n8][1]=0.f; d[mi][n8][2]=0.f; d[mi][n8][3]=0.f; }
#pragma unroll 1
            for (int k0 = 0; k0 < 128; k0 += 16) {
                unsigned bfr0[4], bfr1[4];
                ldsm4(bfr0, bBase + (uint32_t)k0 * 2);                       // tiles 0,1
                ldsm4(bfr1, bBase + (uint32_t)(16 * LDB1 + k0) * 2);         // tiles 2,3
#pragma unroll
                for (int mi = 0; mi < 4; mi++) {
                    if (mi < M) {
                        int m0 = (mstart + cbase + mi) * 16;
                        unsigned av[4];
                        ldsm4(av, aBase + (uint32_t)(m0 * LDA1 + k0) * 2);
                        mma16816(d[mi][0], av, bfr0[0], bfr0[1]);
                        mma16816(d[mi][1], av, bfr0[2], bfr0[3]);
                        mma16816(d[mi][2], av, bfr1[0], bfr1[1]);
                        mma16816(d[mi][3], av, bfr1[2], bfr1[3]);
                    }
                }
            }
#pragma unroll
            for (int mi = 0; mi < 4; mi++) {
                if (mi < M) {
                    int m0 = (mstart + cbase + mi) * 16;
                    int r0 = m0 + g, r1 = m0 + g + 8;
#pragma unroll
                    for (int n8 = 0; n8 < 4; n8++) {
                        int col = s * 32 + n8 * 8 + t4 * 2;
                        *reinterpret_cast<unsigned*>(&A2[r0 * LD2 + col]) =
                            pack2(sigm(d[mi][n8][0] + c1s[col]), sigm(d[mi][n8][1] + c1s[col + 1]));
                        if (r1 < TT)
                            *reinterpret_cast<unsigned*>(&A2[r1 * LD2 + col]) =
                                pack2(sigm(d[mi][n8][2] + c1s[col]), sigm(d[mi][n8][3] + c1s[col + 1]));
                    }
                }
            }
        }
    }
    __syncthreads();

    // ---- phase B setup: W2T into B region (A1 region becomes misc) ----
    for (int t = tid; t < 16384; t += FTH) {
        int j = t >> 7, kk = t & 127;
        *reinterpret_cast<unsigned*>(&Bw[j * LD2 + kk * 2]) = g_imgW2T[t];
    }
    float b3v = b3[0];
    if (tid < 128) {
        s_w3[tid] = w3[tid];
        s_b2[tid] = b2[tid];
        s_lau[tid] = 0.f;
        s_hs[tid] = 0.f;
    }
    if (tid < 208) s_aw[tid] = b3v;
    __syncthreads();

    // ---- GEMM2: warp owns n-strip (32 cols), <=4 m-tiles, LDSM ----
    {
        const int s = wid >> 2;                 // n-strip 0..3
        const int q = wid & 3;                  // m tiles: q, q+4, q+8 (+12 if q==0)
        const int M = (q == 0) ? 4 : 3;
        const uint32_t aBase = smsh + OFF_A2 + (uint32_t)(rowsel * LD2 + kselA) * 2;
        const uint32_t bBase = smsh + OFF_B +
            (uint32_t)((s * 32 + nsel) * LD2 + kselB) * 2;
        float d[4][4][4];
#pragma unroll
        for (int mi = 0; mi < 4; mi++)
            for (int n8 = 0; n8 < 4; n8++)
                { d[mi][n8][0]=0.f; d[mi][n8][1]=0.f; d[mi][n8][2]=0.f; d[mi][n8][3]=0.f; }
#pragma unroll 1
        for (int k0 = 0; k0 < 256; k0 += 16) {
            unsigned bfr0[4], bfr1[4];
            ldsm4(bfr0, bBase + (uint32_t)k0 * 2);
            ldsm4(bfr1, bBase + (uint32_t)(16 * LD2 + k0) * 2);
#pragma unroll
            for (int mi = 0; mi < 4; mi++) {
                if (mi < M) {
                    int m0 = (q + mi * 4) * 16;
                    unsigned av[4];
                    ldsm4(av, aBase + (uint32_t)(m0 * LD2 + k0) * 2);
                    mma16816(d[mi][0], av, bfr0[0], bfr0[1]);
                    mma16816(d[mi][1], av, bfr0[2], bfr0[3]);
                    mma16816(d[mi][2], av, bfr1[0], bfr1[1]);
                    mma16816(d[mi][3], av, bfr1[2], bfr1[3]);
                }
            }
        }
#pragma unroll
        for (int mi = 0; mi < 4; mi++) {
            if (mi < M) {
                int m0 = (q + mi * 4) * 16;
                float p0 = 0.f, p1 = 0.f;
#pragma unroll
                for (int n8 = 0; n8 < 4; n8++) {
                    int c = s * 32 + n8 * 8 + t4 * 2;
                    p0 += sigm(d[mi][n8][0] + s_b2[c]) * s_w3[c]
                        + sigm(d[mi][n8][1] + s_b2[c + 1]) * s_w3[c + 1];
                    p1 += sigm(d[mi][n8][2] + s_b2[c]) * s_w3[c]
                        + sigm(d[mi][n8][3] + s_b2[c + 1]) * s_w3[c + 1];
                }
                p0 += __shfl_xor_sync(0xffffffffu, p0, 1);
                p0 += __shfl_xor_sync(0xffffffffu, p0, 2);
                p1 += __shfl_xor_sync(0xffffffffu, p1, 1);
                p1 += __shfl_xor_sync(0xffffffffu, p1, 2);
                if (t4 == 0) {
                    atomicAdd(&s_aw[m0 + g], p0);
                    if (m0 + g + 8 < TT) atomicAdd(&s_aw[m0 + g + 8], p1);
                }
            }
        }
    }
    __syncthreads();

    // ---- masked softmax over t ----
    int mk = (tid < TT) ? mask[b * TT + tid] : 0;
    {
        float v = -3.0e38f;
        if (tid < TT && mk) v = s_aw[tid];
#pragma unroll
        for (int o = 16; o > 0; o >>= 1)
            v = fmaxf(v, __shfl_xor_sync(0xffffffffu, v, o));
        if (lane == 0) s_red[wid] = v;
        __syncthreads();
        if (tid == 0) {
            float m = s_red[0];
            for (int i = 1; i < 16; i++) m = fmaxf(m, s_red[i]);
            s_scal[0] = m;
        }
        __syncthreads();

        float e = 0.f, cf = 0.f;
        if (tid < TT && mk) { e = __expf(s_aw[tid] - s_scal[0]); cf = 1.f; }
        float se = e, scf = cf;
#pragma unroll
        for (int o = 16; o > 0; o >>= 1) {
            se  += __shfl_xor_sync(0xffffffffu, se, o);
            scf += __shfl_xor_sync(0xffffffffu, scf, o);
        }
        if (lane == 0) { s_red[wid] = se; s_red[16 + wid] = scf; }
        __syncthreads();
        if (tid == 0) {
            float ss = 0.f, cc = 0.f;
            for (int i = 0; i < 16; i++) { ss += s_red[i]; cc += s_red[16 + i]; }
            s_scal[1] = ss; s_scal[2] = cc;
        }
        __syncthreads();
        if (tid < TT) s_aw[tid] = e / s_scal[1];
        __syncthreads();
    }

    // ---- lau + masked sum over history (4 t-slices per column) ----
    {
        int col = tid & 127, quarter = tid >> 7;
        const float* tab = (col < 64) ? mat_table : cat_table;
        const int* hidx = (col < 64) ? hmid : hcat;
        int coff = (col < 64) ? col : (col - 64);
        float al = 0.f, ah = 0.f;
        for (int t2 = quarter; t2 < TT; t2 += 4) {
            int row = hidx[b * TT + t2];
            float h = tab[(size_t)row * EE + coff];
            al += s_aw[t2] * h;
            ah += (float)mask[b * TT + t2] * h;
        }
        atomicAdd(&s_lau[col], al);
        atomicAdd(&s_hs[col], ah);
    }
    __syncthreads();

    // ---- write X row + accumulate column stats for BN0 ----
    if (tid < 448) {
        float inv = 1.0f / s_scal[2];
        int i = tid;
        float v;
        if (i < 64)       v = user_table[(size_t)uid[b] * EE + i];
        else if (i < 192) {
            int c = i - 64;
            v = (c < 64) ? mat_table[(size_t)mid[b] * EE + c]
                         : cat_table[(size_t)catid[b] * EE + c - 64];
        }
        else if (i < 320) v = s_lau[i - 192];
        else              v = s_hs[i - 320] * inv;
        g_X[b * 448 + i] = v;
        atomicAdd(&g_cs[i], v);
        atomicAdd(&g_cq[i], v * v);
    }
}

// =====================================================================
// gemm_bn32: C = f(A) @ W + bias; BN affine computed in-block from cs/cq;
// accumulates per-column sum/sumsq of C into csOut/cqOut
// =====================================================================
__global__ void __launch_bounds__(256) gemm_bn32(
    const float* __restrict__ A, const float* __restrict__ W,
    const float* __restrict__ bias,
    const float* __restrict__ csIn, const float* __restrict__ cqIn,
    const float* __restrict__ gg, const float* __restrict__ bb,
    int leaky, int K, int N,
    float* __restrict__ C, float* __restrict__ csOut, float* __restrict__ cqOut)
{
    __shared__ __align__(16) float Ast[2][32 * 33];
    __shared__ __align__(16) float Bs[2][32 * 64];
    __shared__ float colS[64], colQ[64];
    __shared__ float sSC[512], sSH[512];
    int tid = threadIdx.x;
    int row0 = blockIdx.y * 32, col0 = blockIdx.x * 64;
    int ty = tid >> 4, tx = tid & 15;
    float acc[2][4];
#pragma unroll
    for (int i = 0; i < 2; i++)
        for (int j = 0; j < 4; j++) acc[i][j] = 0.f;

    for (int i = tid; i < K; i += 256) {
        float inv = 1.0f / (float)BB;
        float mu = csIn[i] * inv;
        float var = cqIn[i] * inv - mu * mu;
        float scv = gg[i] * rsqrtf(var + 1e-5f);
        sSC[i] = scv;
        sSH[i] = bb[i] - mu * scv;
    }
    if (tid < 64) { colS[tid] = 0.f; colQ[tid] = 0.f; }
    __syncthreads();

    {
#pragma unroll
        for (int l = 0; l < 4; l++) {
            int i = tid + l * 256;
            int kk = i & 31, r = i >> 5;
            float v = A[(size_t)(row0 + r) * K + kk];
            v = v * sSC[kk] + sSH[kk];
            if (leaky) v = (v > 0.f) ? v : 0.1f * v;
            Ast[0][kk * 33 + r] = v;
        }
#pragma unroll
        for (int l = 0; l < 2; l++) {
            int i = tid + l * 256;
            int kk = i >> 4, c4 = i & 15;
            *reinterpret_cast<float4*>(&Bs[0][kk * 64 + c4 * 4]) =
                *reinterpret_cast<const float4*>(&W[(size_t)kk * N + col0 + c4 * 4]);
        }
    }
    __syncthreads();

    int cur = 0;
    for (int k0 = 0; k0 < K; k0 += 32) {
        int nxt = cur ^ 1;
        if (k0 + 32 < K) {
#pragma unroll
            for (int l = 0; l < 4; l++) {
                int i = tid + l * 256;
                int kk = i & 31, r = i >> 5;
                int k = k0 + 32 + kk;
                float v = A[(size_t)(row0 + r) * K + k];
                v = v * sSC[k] + sSH[k];
                if (leaky) v = (v > 0.f) ? v : 0.1f * v;
                Ast[nxt][kk * 33 + r] = v;
            }
#pragma unroll
            for (int l = 0; l < 2; l++) {
                int i = tid + l * 256;
                int kk = i >> 4, c4 = i & 15;
                *reinterpret_cast<float4*>(&Bs[nxt][kk * 64 + c4 * 4]) =
                    *reinterpret_cast<const float4*>(&W[(size_t)(k0 + 32 + kk) * N + col0 + c4 * 4]);
            }
        }
#pragma unroll 8
        for (int kk = 0; kk < 32; kk++) {
            float a0 = Ast[cur][kk * 33 + ty * 2];
            float a1 = Ast[cur][kk * 33 + ty * 2 + 1];
            float4 bbv = *reinterpret_cast<const float4*>(&Bs[cur][kk * 64 + tx * 4]);
            acc[0][0] += a0 * bbv.x; acc[0][1] += a0 * bbv.y;
            acc[0][2] += a0 * bbv.z; acc[0][3] += a0 * bbv.w;
            acc[1][0] += a1 * bbv.x; acc[1][1] += a1 * bbv.y;
            acc[1][2] += a1 * bbv.z; acc[1][3] += a1 * bbv.w;
        }
        __syncthreads();
        cur = nxt;
    }
    float o[2][4];
#pragma unroll
    for (int i = 0; i < 2; i++) {
        int r = row0 + ty * 2 + i, c = col0 + tx * 4;
        o[i][0] = acc[i][0] + bias[c + 0];
        o[i][1] = acc[i][1] + bias[c + 1];
        o[i][2] = acc[i][2] + bias[c + 2];
        o[i][3] = acc[i][3] + bias[c + 3];
        float4 ov = make_float4(o[i][0], o[i][1], o[i][2], o[i][3]);
        *reinterpret_cast<float4*>(&C[(size_t)r * N + c]) = ov;
    }
#pragma unroll
    for (int j = 0; j < 4; j++) {
        float sv = o[0][j] + o[1][j];
        float qv = o[0][j] * o[0][j] + o[1][j] * o[1][j];
        atomicAdd(&colS[tx * 4 + j], sv);
        atomicAdd(&colQ[tx * 4 + j], qv);
    }
    __syncthreads();
    if (tid < 64) {
        atomicAdd(&csOut[col0 + tid], colS[tid]);
        atomicAdd(&cqOut[col0 + tid], colQ[tid]);
    }
}

// =====================================================================
// final: out[b][0..1] = leaky(bn2(Z2)) @ w3 + b3 ; BN2 affine inline
// =====================================================================
__global__ void __launch_bounds__(256) final_kernel(
    const float* __restrict__ csIn, const float* __restrict__ cqIn,
    const float* __restrict__ gg, const float* __restrict__ bb,
    const float* __restrict__ w3, const float* __restrict__ b3,
    float* __restrict__ out)
{
    int b = blockIdx.x, tid = threadIdx.x;
    int lane = tid & 31, w = tid >> 5;
    float inv = 1.0f / (float)BB;
    float mu = csIn[tid] * inv;
    float var = cqIn[tid] * inv - mu * mu;
    float scv = gg[tid] * rsqrtf(var + 1e-5f);
    float v = g_Z2[b * 256 + tid] * scv + (bb[tid] - mu * scv);
    v = (v > 0.f) ? v : 0.1f * v;
    float a0 = v * w3[tid * 2 + 0];
    float a1 = v * w3[tid * 2 + 1];
#pragma unroll
    for (int o = 16; o > 0; o >>= 1) {
        a0 += __shfl_xor_sync(0xffffffffu, a0, o);
        a1 += __shfl_xor_sync(0xffffffffu, a1, o);
    }
    __shared__ float r0s[8], r1s[8];
    if (lane == 0) { r0s[w] = a0; r1s[w] = a1; }
    __syncthreads();
    if (tid == 0) {
        float s0 = 0.f, s1 = 0.f;
        for (int i = 0; i < 8; i++) { s0 += r0s[i]; s1 += r1s[i]; }
        out[b * 2 + 0] = s0 + b3[0];
        out[b * 2 + 1] = s1 + b3[1];
    }
}

// =====================================================================
extern "C" void kernel_launch(void* const* d_in, const int* in_sizes, int n_in,
                              void* d_out, int out_size)
{
    (void)in_sizes; (void)n_in; (void)out_size;
    const int*   uid   = (const int*)d_in[0];
    const int*   mid   = (const int*)d_in[1];
    const int*   cat   = (const int*)d_in[2];
    const int*   hmid  = (const int*)d_in[3];
    const int*   hcat  = (const int*)d_in[4];
    const int*   mask  = (const int*)d_in[5];
    const float* utab  = (const float*)d_in[6];
    const float* mtab  = (const float*)d_in[7];
    const float* ctab  = (const float*)d_in[8];
    const float* lw1   = (const float*)d_in[9];
    const float* lb1   = (const float*)d_in[10];
    const float* lw2   = (const float*)d_in[11];
    const float* lb2   = (const float*)d_in[12];
    const float* lw3   = (const float*)d_in[13];
    const float* lb3   = (const float*)d_in[14];
    const float* bn0g  = (const float*)d_in[15];
    const float* bn0b  = (const float*)d_in[16];
    const float* mw1   = (const float*)d_in[17];
    const float* mb1   = (const float*)d_in[18];
    const float* bn1g  = (const float*)d_in[19];
    const float* bn1b  = (const float*)d_in[20];
    const float* mw2   = (const float*)d_in[21];
    const float* mb2   = (const float*)d_in[22];
    const float* bn2g  = (const float*)d_in[23];
    const float* bn2b  = (const float*)d_in[24];
    const float* mw3   = (const float*)d_in[25];
    const float* mb3   = (const float*)d_in[26];
    float* out = (float*)d_out;

    static int attr_done = 0;
    if (!attr_done) {
        cudaFuncSetAttribute(fused_kernel, cudaFuncAttributeMaxDynamicSharedMemorySize,
                             FUSED_SMEM);
        attr_done = 1;
    }

    float *X, *Z1, *Z2, *cs, *cq;
    cudaGetSymbolAddress((void**)&X,  g_X);
    cudaGetSymbolAddress((void**)&Z1, g_Z1);
    cudaGetSymbolAddress((void**)&Z2, g_Z2);
    cudaGetSymbolAddress((void**)&cs, g_cs);
    cudaGetSymbolAddress((void**)&cq, g_cq);

    prep_all<<<192, 256>>>(lw1, lw2);

    fused_kernel<<<BB, FTH, FUSED_SMEM>>>(uid, mid, cat, hmid, hcat, mask,
                                          utab, mtab, ctab, lb1, lb2, lw3, lb3);

    gemm_bn32<<<dim3(512 / 64, BB / 32), 256>>>(X, mw1, mb1, cs, cq, bn0g, bn0b,
                                                0, 448, 512, Z1, cs + 448, cq + 448);

    gemm_bn32<<<dim3(256 / 64, BB / 32), 256>>>(Z1, mw2, mb2, cs + 448, cq + 448,
                                                bn1g, bn1b, 1, 512, 256,
                                                Z2, cs + 960, cq + 960);

    final_kernel<<<BB, 256>>>(cs + 960, cq + 960, bn2g, bn2b, mw3, mb3, out);
}